// round 3
// baseline (speedup 1.0000x reference)
#include <cuda_runtime.h>

#define NN      262144          // 64^3
#define NNZ_TOT (7 * NN)
#define BS      128
#define CH      32              // batch chunk width
#define NCHUNK  (BS / CH)       // 4
#define RPW     16              // rows per warp in fused kernel
#define FBLOCKS (NN / (8 * RPW))// 2048

// Scratch (allocation-free rule)
__device__ float  g_ypT[(size_t)NN * CH];   // y_pred chunk, (N, 32)  32 MB
__device__ float  g_ytT[(size_t)NN * CH];   // y_true chunk, (N, 32)  32 MB
__device__ int    g_cnt[NN];
__device__ int    g_off[NN + 1];
__device__ int    g_fill[NN];
__device__ int2   g_csr[NNZ_TOT];           // (col, val-bits) sorted by row, 14.7 MB
__device__ int    g_bsum[256];
__device__ double g_acc[5 * BS];

// ---------------------------------------------------------------- zeroing
__global__ void zero_acc_kernel() { g_acc[threadIdx.x] = 0.0; }           // 640 thr
__global__ void zero_cnt_kernel() {
    int i = blockIdx.x * blockDim.x + threadIdx.x;
    if (i < NN) g_cnt[i] = 0;
}

// ------------------------------------------------------------- histogram
__global__ void hist_kernel(const int* __restrict__ rows) {
    int i = blockIdx.x * blockDim.x + threadIdx.x;
    int stride = gridDim.x * blockDim.x;
    for (; i < NNZ_TOT; i += stride)
        atomicAdd(&g_cnt[__ldcs(rows + i)], 1);
}

// ------------------------------------------------- block scan primitives
__device__ __forceinline__ int blockExclScan256(int local, int tid) {
    int lane = tid & 31, w = tid >> 5;
    int inc = local;
#pragma unroll
    for (int d = 1; d < 32; d <<= 1) {
        int n = __shfl_up_sync(0xffffffffu, inc, d);
        if (lane >= d) inc += n;
    }
    __shared__ int wsum[8];
    if (lane == 31) wsum[w] = inc;
    __syncthreads();
    if (tid == 0) {
        int run = 0;
#pragma unroll
        for (int k = 0; k < 8; k++) { int t = wsum[k]; wsum[k] = run; run += t; }
    }
    __syncthreads();
    return inc - local + wsum[w];   // exclusive prefix
}

// scan stage 1: per-block (1024 counts) totals -> g_bsum[256]
__global__ void scan_reduce_kernel() {
    int tid = threadIdx.x;
    int4 v = ((const int4*)g_cnt)[blockIdx.x * 256 + tid];
    int local = v.x + v.y + v.z + v.w;
    // block reduce
    int lane = tid & 31, w = tid >> 5;
    int s = local;
#pragma unroll
    for (int d = 16; d > 0; d >>= 1) s += __shfl_down_sync(0xffffffffu, s, d);
    __shared__ int wsum[8];
    if (lane == 0) wsum[w] = s;
    __syncthreads();
    if (tid == 0) {
        int tot = 0;
#pragma unroll
        for (int k = 0; k < 8; k++) tot += wsum[k];
        g_bsum[blockIdx.x] = tot;
    }
}

// scan stage 2: exclusive scan of 256 block sums (single block)
__global__ void scan_top_kernel() {
    int tid = threadIdx.x;
    int v = g_bsum[tid];
    int e = blockExclScan256(v, tid);
    __syncthreads();
    g_bsum[tid] = e;
}

// scan stage 3: final offsets + fill cursors
__global__ void scan_spread_kernel() {
    int tid = threadIdx.x;
    int gbase = blockIdx.x * 1024 + tid * 4;
    int4 v = ((const int4*)g_cnt)[blockIdx.x * 256 + tid];
    int local = v.x + v.y + v.z + v.w;
    int pre = blockExclScan256(local, tid);
    int o = g_bsum[blockIdx.x] + pre;
    g_off[gbase + 0] = o;           g_fill[gbase + 0] = o;       o += v.x;
    g_off[gbase + 1] = o;           g_fill[gbase + 1] = o;       o += v.y;
    g_off[gbase + 2] = o;           g_fill[gbase + 2] = o;       o += v.z;
    g_off[gbase + 3] = o;           g_fill[gbase + 3] = o;
    if (blockIdx.x == 0 && tid == 0) g_off[NN] = NNZ_TOT;
}

// ---------------------------------------------------------------- CSR fill
__global__ void fill_kernel(const float* __restrict__ vals,
                            const int* __restrict__ rows,
                            const int* __restrict__ cols) {
    int i = blockIdx.x * blockDim.x + threadIdx.x;
    int stride = gridDim.x * blockDim.x;
    for (; i < NNZ_TOT; i += stride) {
        int r = __ldcs(rows + i);
        int pos = atomicAdd(&g_fill[r], 1);
        g_csr[pos] = make_int2(__ldcs(cols + i),
                               __float_as_int(__ldcs(vals + i)));
    }
}

// ---------------- per-chunk prep: transpose yp AND yt chunks (N, 32)
__global__ void prep_chunk(const float* __restrict__ yp,
                           const float* __restrict__ yt, int b0) {
    __shared__ float tp[32][33];
    __shared__ float tt[32][33];
    int n0 = blockIdx.x * 32;
    int tx = threadIdx.x, ty = threadIdx.y;       // block (32, 8)
#pragma unroll
    for (int r = 0; r < 32; r += 8) {
        size_t src = (size_t)(b0 + ty + r) * NN + n0 + tx;
        tp[ty + r][tx] = __ldcs(yp + src);        // streaming: don't pollute L2
        tt[ty + r][tx] = __ldcs(yt + src);
    }
    __syncthreads();
#pragma unroll
    for (int r = 0; r < 32; r += 8) {
        size_t dst = (size_t)(n0 + ty + r) * 32 + tx;
        g_ypT[dst] = tp[tx][ty + r];
        g_ytT[dst] = tt[tx][ty + r];
    }
}

// ---------------- fused SpMV + reductions, no Yhat materialization.
// One warp owns RPW consecutive rows; lane = batch element within chunk.
// h (Yhat row) lives in a register; s1..s5 accumulated directly.
__global__ void fused_chunk(int b0) {
    int tid  = threadIdx.x;
    int lane = tid & 31;
    int w    = tid >> 5;                          // 8 warps
    int wg   = blockIdx.x * 8 + w;
    int rbase = wg * RPW;

    int offv = (lane <= RPW) ? g_off[rbase + lane] : 0;

    float a1 = 0.f, a2 = 0.f, a3 = 0.f, a4 = 0.f, a5 = 0.f;
#pragma unroll 1
    for (int i = 0; i < RPW; i++) {
        int beg = __shfl_sync(0xffffffffu, offv, i);
        int end = __shfl_sync(0xffffffffu, offv, i + 1);
        float h = 0.f;
        for (int q = beg; q < end; q++) {
            int2 cv = __ldg(&g_csr[q]);
            h += __int_as_float(cv.y) * __ldg(&g_ypT[(size_t)cv.x * 32 + lane]);
        }
        size_t rb = (size_t)(rbase + i) * 32 + lane;
        float p = g_ypT[rb];
        float t = g_ytT[rb];
        a1 += t * p;
        a2 += p * h;
        a3 += t * t;
        a4 += t * h;
        a5 += h * h;
    }

    __shared__ float red[5][8][32];
    red[0][w][lane] = a1;
    red[1][w][lane] = a2;
    red[2][w][lane] = a3;
    red[3][w][lane] = a4;
    red[4][w][lane] = a5;
    __syncthreads();

    if (tid < 160) {
        int acc = tid >> 5;
        int j   = tid & 31;
        float s = 0.f;
#pragma unroll
        for (int ww = 0; ww < 8; ww++) s += red[acc][ww][j];
        atomicAdd(&g_acc[acc * BS + b0 + j], (double)s);
    }
}

// ------------------------------------------------------------ final scalar
__global__ void final_kernel(float* out) {
    int b = threadIdx.x;            // 128 threads
    double s1 = g_acc[0 * BS + b];
    double s2 = g_acc[1 * BS + b];
    double s3 = g_acc[2 * BS + b];
    double s4 = g_acc[3 * BS + b];
    double s5 = g_acc[4 * BS + b];
    double c  = s1 / s2;
    double r  = s3 - 2.0 * c * s4 + c * c * s5;
    __shared__ double sh[128];
    sh[b] = r;
    __syncthreads();
    for (int s = 64; s > 0; s >>= 1) {
        if (b < s) sh[b] += sh[b + s];
        __syncthreads();
    }
    if (b == 0) out[0] = (float)(sh[0] / (double)BS);
}

extern "C" void kernel_launch(void* const* d_in, const int* in_sizes, int n_in,
                              void* d_out, int out_size) {
    const float* yp   = (const float*)d_in[0];
    const float* yt   = (const float*)d_in[1];
    const float* vals = (const float*)d_in[2];
    const int*   rows = (const int*)d_in[3];
    const int*   cols = (const int*)d_in[4];
    float*       out  = (float*)d_out;

    // --- one-time (per call) CSR build ---
    zero_acc_kernel<<<1, 5 * BS>>>();
    zero_cnt_kernel<<<NN / 256, 256>>>();
    hist_kernel<<<1184, 256>>>(rows);
    scan_reduce_kernel<<<256, 256>>>();
    scan_top_kernel<<<1, 256>>>();
    scan_spread_kernel<<<256, 256>>>();
    fill_kernel<<<1184, 256>>>(vals, rows, cols);

    // --- 4 batch chunks, L2-resident working set ---
    for (int c = 0; c < NCHUNK; c++) {
        int b0 = c * CH;
        prep_chunk<<<NN / 32, dim3(32, 8)>>>(yp, yt, b0);
        fused_chunk<<<FBLOCKS, 256>>>(b0);
    }
    final_kernel<<<1, BS>>>(out);
}